// round 2
// baseline (speedup 1.0000x reference)
#include <cuda_runtime.h>
#include <cstdint>

typedef unsigned long long u64;

// ---------------- problem constants ----------------
#define BATCH 16
#define TOK   1024
#define FEAT_ 1024
#define RANK_ 8
// per-batch factor block: 4 * D * R = 32768 floats
#define WSTRIDE 32768

// ---------------- device scratch (no allocs allowed) ----------------
__device__ float g_lnT[1024 * 16];   // LN(ada) transposed: [k][b]
__device__ float g_hT [1024 * 16];   // h transposed: [k][b]
__device__ float g_w  [16 * 32768];  // per-batch factors a1|bb1|a2|bb2, [b][d*8+r]

// ---------------- f32x2 helpers ----------------
__device__ __forceinline__ u64 pk2(float lo, float hi) {
    u64 r; asm("mov.b64 %0, {%1,%2};" : "=l"(r) : "f"(lo), "f"(hi)); return r;
}
__device__ __forceinline__ void upk2(u64 v, float& lo, float& hi) {
    asm("mov.b64 {%0,%1}, %2;" : "=f"(lo), "=f"(hi) : "l"(v));
}
__device__ __forceinline__ u64 dup2(float x) { return pk2(x, x); }
__device__ __forceinline__ u64 fma2(u64 a, u64 b, u64 c) {
    u64 d; asm("fma.rn.f32x2 %0, %1, %2, %3;" : "=l"(d) : "l"(a), "l"(b), "l"(c)); return d;
}
__device__ __forceinline__ u64 mul2(u64 a, u64 b) {
    u64 d; asm("mul.rn.f32x2 %0, %1, %2;" : "=l"(d) : "l"(a), "l"(b)); return d;
}
__device__ __forceinline__ u64 add2(u64 a, u64 b) {
    u64 d; asm("add.rn.f32x2 %0, %1, %2;" : "=l"(d) : "l"(a), "l"(b)); return d;
}
__device__ __forceinline__ float rcpa(float x) {
    float r; asm("rcp.approx.f32 %0, %1;" : "=f"(r) : "f"(x)); return r;
}
__device__ __forceinline__ float ex2a(float x) {
    float r; asm("ex2.approx.f32 %0, %1;" : "=f"(r) : "f"(x)); return r;
}

// exact gelu, scalar (erff-based); used only in the tiny hypernet stage
__device__ __forceinline__ float gelu1(float v) {
    return 0.5f * v * (1.0f + erff(v * 0.7071067811865476f));
}

// exact gelu on a packed f32x2 pair via Abramowitz-Stegun 7.1.26 erf
// (max abs err 1.5e-7, far below the 1e-3 tolerance). MUFU rcp/ex2 + FMA2 poly.
__device__ __forceinline__ u64 gelu2(u64 v) {
    u64 s  = mul2(v, dup2(0.7071067811865476f));
    u64 x  = s & 0x7FFFFFFF7FFFFFFFULL;                 // |s| per half
    u64 dn = fma2(x, dup2(0.3275911f), dup2(1.0f));
    float d0, d1; upk2(dn, d0, d1);
    u64 t  = pk2(rcpa(d0), rcpa(d1));
    // negated Horner poly: -P(t)
    u64 p  = fma2(t, dup2(-1.061405429f), dup2(1.453152027f));
    p = fma2(p, t, dup2(-1.421413741f));
    p = fma2(p, t, dup2( 0.284496736f));
    p = fma2(p, t, dup2(-0.254829592f));
    p = mul2(p, t);
    // e = exp(-x^2) = 2^(-x^2*log2e)
    u64 xx = mul2(x, x);
    u64 ea = mul2(xx, dup2(-1.4426950408889634f));
    float e0, e1; upk2(ea, e0, e1);
    u64 e  = pk2(ex2a(e0), ex2a(e1));
    u64 erfa = fma2(p, e, dup2(1.0f));                  // 1 - P*e  (>= -eps)
    u64 sgn  = s & 0x8000000080000000ULL;
    u64 erf  = erfa | sgn;                              // copysign
    u64 h    = fma2(erf, dup2(0.5f), dup2(0.5f));
    return mul2(v, h);
}

// butterfly all-reduce of a packed pair across the warp
__device__ __forceinline__ void allred2(u64& v) {
    #pragma unroll
    for (int off = 16; off > 0; off >>= 1) {
        u64 o = __shfl_xor_sync(0xFFFFFFFFu, v, off);
        v = add2(v, o);
    }
}

// ============================================================================
// Kernel 0: LayerNorm of ada_emb -> g_lnT[k][b]  (pre-transposed for GEMM1)
// ============================================================================
__global__ __launch_bounds__(256)
void ln_kernel(const float* __restrict__ ada, const float* __restrict__ lg,
               const float* __restrict__ lb) {
    __shared__ float red[8];
    const int b = blockIdx.x, tid = threadIdx.x;
    const int lane = tid & 31, wrp = tid >> 5;

    float a[4];
    #pragma unroll
    for (int j = 0; j < 4; ++j) a[j] = ada[b * 1024 + tid + 256 * j];

    float s = a[0] + a[1] + a[2] + a[3];
    #pragma unroll
    for (int off = 16; off > 0; off >>= 1) s += __shfl_xor_sync(~0u, s, off);
    if (lane == 0) red[wrp] = s;
    __syncthreads();
    float mu = 0.f;
    #pragma unroll
    for (int w = 0; w < 8; ++w) mu += red[w];
    mu *= (1.0f / 1024.0f);
    __syncthreads();

    float ss = 0.f;
    #pragma unroll
    for (int j = 0; j < 4; ++j) { float d = a[j] - mu; ss += d * d; }
    #pragma unroll
    for (int off = 16; off > 0; off >>= 1) ss += __shfl_xor_sync(~0u, ss, off);
    if (lane == 0) red[wrp] = ss;
    __syncthreads();
    float var = 0.f;
    #pragma unroll
    for (int w = 0; w < 8; ++w) var += red[w];
    var *= (1.0f / 1024.0f);
    const float rs = rsqrtf(var + 1e-5f);

    #pragma unroll
    for (int j = 0; j < 4; ++j) {
        int k = tid + 256 * j;
        g_lnT[k * 16 + b] = (a[j] - mu) * rs * lg[k] + lb[k];
    }
}

// ============================================================================
// Kernel 1: h = gelu(LN @ W1 + b1) -> g_hT[k][b]   [16x1024 @ 1024x1024]
// grid 32 CTAs x 256 thr; CTA covers 32 cols; 8-way k-split; f32x2 over batch.
// ============================================================================
__global__ __launch_bounds__(256)
void h_kernel(const float* __restrict__ W1, const float* __restrict__ b1) {
    extern __shared__ float s[];   // 16384 floats (64KB), reused for reduction
    const int tid = threadIdx.x;
    for (int i = tid; i < 16384; i += 256) s[i] = g_lnT[i];
    __syncthreads();

    const int kg = tid >> 5, cl = tid & 31;
    const int col = (blockIdx.x << 5) + cl;

    u64 acc[8];
    #pragma unroll
    for (int j = 0; j < 8; ++j) acc[j] = 0ULL;

    #pragma unroll 8
    for (int k = kg; k < 1024; k += 8) {
        float w = __ldg(W1 + k * 1024 + col);
        u64 wd = dup2(w);
        const ulonglong2* hp = (const ulonglong2*)(s + k * 16);
        #pragma unroll
        for (int m = 0; m < 4; ++m) {
            ulonglong2 p = hp[m];
            acc[2 * m]     = fma2(p.x, wd, acc[2 * m]);
            acc[2 * m + 1] = fma2(p.y, wd, acc[2 * m + 1]);
        }
    }
    __syncthreads();
    #pragma unroll
    for (int j = 0; j < 8; ++j) {
        float f0, f1; upk2(acc[j], f0, f1);
        s[tid * 17 + 2 * j]     = f0;
        s[tid * 17 + 2 * j + 1] = f1;
    }
    __syncthreads();

    const int oc = tid & 31, ob = tid >> 5;      // ob in 0..7
    const int ocol = (blockIdx.x << 5) + oc;
    float v0 = b1[ocol], v1 = b1[ocol];
    #pragma unroll
    for (int g = 0; g < 8; ++g) {
        const float* p = s + (g * 32 + oc) * 17;
        v0 += p[ob];
        v1 += p[ob + 8];
    }
    g_hT[ocol * 16 + ob]     = gelu1(v0);
    g_hT[ocol * 16 + ob + 8] = gelu1(v1);
}

// ============================================================================
// Kernel 2: w = h @ W2 + b2 -> g_w  [16x1024 @ 1024x32768] — DRAM-bound on W2
// grid 1024 CTAs x 256 thr; 32 cols/CTA; f32x2 over batch pairs.
// ============================================================================
__global__ __launch_bounds__(256)
void w_kernel(const float* __restrict__ W2, const float* __restrict__ b2) {
    extern __shared__ float s[];   // 16384 floats (64KB), reused for reduction
    const int tid = threadIdx.x;
    for (int i = tid; i < 16384; i += 256) s[i] = g_hT[i];
    __syncthreads();

    const int kg = tid >> 5, cl = tid & 31;
    const int col = (blockIdx.x << 5) + cl;

    u64 acc[8];
    #pragma unroll
    for (int j = 0; j < 8; ++j) acc[j] = 0ULL;

    #pragma unroll 8
    for (int k = kg; k < 1024; k += 8) {
        float w = __ldg(W2 + (size_t)k * 32768 + col);
        u64 wd = dup2(w);
        const ulonglong2* hp = (const ulonglong2*)(s + k * 16);
        #pragma unroll
        for (int m = 0; m < 4; ++m) {
            ulonglong2 p = hp[m];
            acc[2 * m]     = fma2(p.x, wd, acc[2 * m]);
            acc[2 * m + 1] = fma2(p.y, wd, acc[2 * m + 1]);
        }
    }
    __syncthreads();
    #pragma unroll
    for (int j = 0; j < 8; ++j) {
        float f0, f1; upk2(acc[j], f0, f1);
        s[tid * 17 + 2 * j]     = f0;
        s[tid * 17 + 2 * j + 1] = f1;
    }
    __syncthreads();

    const int oc = tid & 31, ob = tid >> 5;
    const int ocol = (blockIdx.x << 5) + oc;
    float v0 = b2[ocol], v1 = b2[ocol];
    #pragma unroll
    for (int g = 0; g < 8; ++g) {
        const float* p = s + (g * 32 + oc) * 17;
        v0 += p[ob];
        v1 += p[ob + 8];
    }
    g_w[ob * WSTRIDE + ocol]       = v0;
    g_w[(ob + 8) * WSTRIDE + ocol] = v1;
}

// ============================================================================
// Kernel 3: fused main path. CTA = 128 thr (4 warps), 8 rows/warp, 32 rows/CTA.
// grid = 512 (16 batches x 32 row-chunks). Phases:
//   P1: t1[row][r] = sum_d x*a1        (a1 transposed in smem)
//   P2: t2[row][r] = sum_d gelu(t1.bb1[d]) * a2[d]
//   P3: out = t2.bb2[d] + x
// x read once from DRAM (+ L1/L2 re-hit in P3), out written once.
// ============================================================================
#define SROW 1028   // padded row stride for transposed factors (conflict-free)

__global__ __launch_bounds__(128, 2)
void main_kernel(const float* __restrict__ x, float* __restrict__ out) {
    extern __shared__ float smem[];
    float* sA = smem;               // 8 * SROW
    float* sB = smem + 8 * SROW;    // 8 * SROW

    const int tid  = threadIdx.x;
    const int lane = tid & 31, wrp = tid >> 5;
    const int b    = blockIdx.x >> 5;
    const int t0   = (blockIdx.x & 31) << 5;
    const int row0 = t0 + wrp * 8;
    const float* gw = g_w + b * WSTRIDE;

    // ---- load a1 transposed: sA[r][d] ----
    for (int i = tid; i < 8192; i += 128)
        sA[(i & 7) * SROW + (i >> 3)] = gw[i];
    __syncthreads();

    const float* xr = x + (b * 1024 + row0) * 1024;

    // ---- P1: t1 ----
    u64 t1[4][8];
    #pragma unroll
    for (int j = 0; j < 4; ++j)
        #pragma unroll
        for (int r = 0; r < 8; ++r) t1[j][r] = 0ULL;

    #pragma unroll 2
    for (int i = 0; i < 32; ++i) {
        const int d = lane + (i << 5);
        float av[8];
        #pragma unroll
        for (int r = 0; r < 8; ++r) av[r] = sA[r * SROW + d];
        float xv[8];
        #pragma unroll
        for (int rr = 0; rr < 8; ++rr) xv[rr] = __ldg(xr + rr * 1024 + d);
        u64 xp[4];
        #pragma unroll
        for (int j = 0; j < 4; ++j) xp[j] = pk2(xv[2 * j], xv[2 * j + 1]);
        #pragma unroll
        for (int r = 0; r < 8; ++r) {
            u64 ad = dup2(av[r]);
            #pragma unroll
            for (int j = 0; j < 4; ++j) t1[j][r] = fma2(xp[j], ad, t1[j][r]);
        }
    }
    #pragma unroll
    for (int j = 0; j < 4; ++j)
        #pragma unroll
        for (int r = 0; r < 8; ++r) allred2(t1[j][r]);

    // ---- load bb1 -> sA, a2 -> sB ----
    __syncthreads();
    for (int i = tid; i < 8192; i += 128) {
        const int r = i & 7, d = i >> 3;
        sA[r * SROW + d] = gw[8192 + i];
        sB[r * SROW + d] = gw[16384 + i];
    }
    __syncthreads();

    // ---- P2: t2 ----
    u64 t2[4][8];
    #pragma unroll
    for (int j = 0; j < 4; ++j)
        #pragma unroll
        for (int r = 0; r < 8; ++r) t2[j][r] = 0ULL;

    #pragma unroll 1
    for (int i = 0; i < 32; ++i) {
        const int d = lane + (i << 5);
        float bv[8], av[8];
        #pragma unroll
        for (int r = 0; r < 8; ++r) { bv[r] = sA[r * SROW + d]; av[r] = sB[r * SROW + d]; }
        u64 z[4] = {0ULL, 0ULL, 0ULL, 0ULL};
        #pragma unroll
        for (int r = 0; r < 8; ++r) {
            u64 bd = dup2(bv[r]);
            #pragma unroll
            for (int j = 0; j < 4; ++j) z[j] = fma2(t1[j][r], bd, z[j]);
        }
        #pragma unroll
        for (int j = 0; j < 4; ++j) z[j] = gelu2(z[j]);
        #pragma unroll
        for (int r = 0; r < 8; ++r) {
            u64 ad = dup2(av[r]);
            #pragma unroll
            for (int j = 0; j < 4; ++j) t2[j][r] = fma2(z[j], ad, t2[j][r]);
        }
    }
    #pragma unroll
    for (int j = 0; j < 4; ++j)
        #pragma unroll
        for (int r = 0; r < 8; ++r) allred2(t2[j][r]);

    // ---- load bb2 -> sA ----
    __syncthreads();
    for (int i = tid; i < 8192; i += 128)
        sA[(i & 7) * SROW + (i >> 3)] = gw[24576 + i];
    __syncthreads();

    // ---- P3: out = t2 . bb2 + x ----
    float* orow = out + (b * 1024 + row0) * 1024;
    #pragma unroll 2
    for (int i = 0; i < 32; ++i) {
        const int d = lane + (i << 5);
        float bv[8];
        #pragma unroll
        for (int r = 0; r < 8; ++r) bv[r] = sA[r * SROW + d];
        float xv[8];
        #pragma unroll
        for (int rr = 0; rr < 8; ++rr) xv[rr] = __ldg(xr + rr * 1024 + d);
        u64 o[4];
        #pragma unroll
        for (int j = 0; j < 4; ++j) o[j] = pk2(xv[2 * j], xv[2 * j + 1]);
        #pragma unroll
        for (int r = 0; r < 8; ++r) {
            u64 bd = dup2(bv[r]);
            #pragma unroll
            for (int j = 0; j < 4; ++j) o[j] = fma2(t2[j][r], bd, o[j]);
        }
        #pragma unroll
        for (int j = 0; j < 4; ++j) {
            float f0, f1; upk2(o[j], f0, f1);
            orow[(2 * j) * 1024 + d]     = f0;
            orow[(2 * j + 1) * 1024 + d] = f1;
        }
    }
}

// ============================================================================
// launch
// ============================================================================
extern "C" void kernel_launch(void* const* d_in, const int* in_sizes, int n_in,
                              void* d_out, int out_size) {
    const float* x    = (const float*)d_in[0];
    const float* ada  = (const float*)d_in[1];
    const float* ln_g = (const float*)d_in[2];
    const float* ln_b = (const float*)d_in[3];
    const float* W1   = (const float*)d_in[4];
    const float* b1   = (const float*)d_in[5];
    const float* W2   = (const float*)d_in[6];
    const float* b2   = (const float*)d_in[7];
    float* out = (float*)d_out;

    cudaFuncSetAttribute(h_kernel,    cudaFuncAttributeMaxDynamicSharedMemorySize, 65536);
    cudaFuncSetAttribute(w_kernel,    cudaFuncAttributeMaxDynamicSharedMemorySize, 65536);
    cudaFuncSetAttribute(main_kernel, cudaFuncAttributeMaxDynamicSharedMemorySize, 2 * 8 * SROW * 4);

    ln_kernel<<<16, 256>>>(ada, ln_g, ln_b);
    h_kernel<<<32, 256, 65536>>>(W1, b1);
    w_kernel<<<1024, 256, 65536>>>(W2, b2);
    main_kernel<<<512, 128, 2 * 8 * SROW * 4>>>(x, out);
}

// round 4
// speedup vs baseline: 1.3130x; 1.3130x over previous
#include <cuda_runtime.h>
#include <cstdint>

typedef unsigned long long u64;

// ---------------- problem constants ----------------
#define BATCH 16
#define WSTRIDE 32768   // per-batch factor block: 4 * 1024 * 8

// ---------------- device scratch ----------------
__device__ float g_lnT[1024 * 16];   // LN(ada) transposed: [k][b]
__device__ float g_hT [1024 * 16];   // h transposed: [k][b]
// factors, PRE-TRANSPOSED: [b][f][r][d], f: 0=a1, 1=bb1, 2=a2, 3=bb2
__device__ float g_w  [16 * 32768];

// ---------------- f32x2 helpers ----------------
__device__ __forceinline__ u64 pk2(float lo, float hi) {
    u64 r; asm("mov.b64 %0, {%1,%2};" : "=l"(r) : "f"(lo), "f"(hi)); return r;
}
__device__ __forceinline__ void upk2(u64 v, float& lo, float& hi) {
    asm("mov.b64 {%0,%1}, %2;" : "=f"(lo), "=f"(hi) : "l"(v));
}
__device__ __forceinline__ u64 dup2(float x) { return pk2(x, x); }
__device__ __forceinline__ u64 fma2(u64 a, u64 b, u64 c) {
    u64 d; asm("fma.rn.f32x2 %0, %1, %2, %3;" : "=l"(d) : "l"(a), "l"(b), "l"(c)); return d;
}
__device__ __forceinline__ u64 mul2(u64 a, u64 b) {
    u64 d; asm("mul.rn.f32x2 %0, %1, %2;" : "=l"(d) : "l"(a), "l"(b)); return d;
}
__device__ __forceinline__ u64 add2(u64 a, u64 b) {
    u64 d; asm("add.rn.f32x2 %0, %1, %2;" : "=l"(d) : "l"(a), "l"(b)); return d;
}
__device__ __forceinline__ float rcpa(float x) {
    float r; asm("rcp.approx.f32 %0, %1;" : "=f"(r) : "f"(x)); return r;
}
__device__ __forceinline__ float ex2a(float x) {
    float r; asm("ex2.approx.f32 %0, %1;" : "=f"(r) : "f"(x)); return r;
}

__device__ __forceinline__ float gelu1(float v) {
    return 0.5f * v * (1.0f + erff(v * 0.7071067811865476f));
}

// exact gelu on packed f32x2 via A&S 7.1.26 erf (abs err 1.5e-7)
__device__ __forceinline__ u64 gelu2(u64 v) {
    u64 s  = mul2(v, dup2(0.7071067811865476f));
    u64 x  = s & 0x7FFFFFFF7FFFFFFFULL;
    u64 dn = fma2(x, dup2(0.3275911f), dup2(1.0f));
    float d0, d1; upk2(dn, d0, d1);
    u64 t  = pk2(rcpa(d0), rcpa(d1));
    u64 p  = fma2(t, dup2(-1.061405429f), dup2(1.453152027f));
    p = fma2(p, t, dup2(-1.421413741f));
    p = fma2(p, t, dup2( 0.284496736f));
    p = fma2(p, t, dup2(-0.254829592f));
    p = mul2(p, t);
    u64 xx = mul2(x, x);
    u64 ea = mul2(xx, dup2(-1.4426950408889634f));
    float e0, e1; upk2(ea, e0, e1);
    u64 e  = pk2(ex2a(e0), ex2a(e1));
    u64 erfa = fma2(p, e, dup2(1.0f));
    u64 sgn  = s & 0x8000000080000000ULL;
    u64 erf  = erfa | sgn;
    u64 h    = fma2(erf, dup2(0.5f), dup2(0.5f));
    return mul2(v, h);
}

__device__ __forceinline__ void allred2(u64& v) {
    #pragma unroll
    for (int off = 16; off > 0; off >>= 1) {
        u64 o = __shfl_xor_sync(0xFFFFFFFFu, v, off);
        v = add2(v, o);
    }
}

// ============================================================================
// Kernel 0: LayerNorm -> g_lnT[k][b]
// ============================================================================
__global__ __launch_bounds__(256)
void ln_kernel(const float* __restrict__ ada, const float* __restrict__ lg,
               const float* __restrict__ lb) {
    __shared__ float red[8];
    const int b = blockIdx.x, tid = threadIdx.x;
    const int lane = tid & 31, wrp = tid >> 5;

    float a[4];
    #pragma unroll
    for (int j = 0; j < 4; ++j) a[j] = ada[b * 1024 + tid + 256 * j];

    float s = a[0] + a[1] + a[2] + a[3];
    #pragma unroll
    for (int off = 16; off > 0; off >>= 1) s += __shfl_xor_sync(~0u, s, off);
    if (lane == 0) red[wrp] = s;
    __syncthreads();
    float mu = 0.f;
    #pragma unroll
    for (int w = 0; w < 8; ++w) mu += red[w];
    mu *= (1.0f / 1024.0f);
    __syncthreads();

    float ss = 0.f;
    #pragma unroll
    for (int j = 0; j < 4; ++j) { float d = a[j] - mu; ss += d * d; }
    #pragma unroll
    for (int off = 16; off > 0; off >>= 1) ss += __shfl_xor_sync(~0u, ss, off);
    if (lane == 0) red[wrp] = ss;
    __syncthreads();
    float var = 0.f;
    #pragma unroll
    for (int w = 0; w < 8; ++w) var += red[w];
    var *= (1.0f / 1024.0f);
    const float rs = rsqrtf(var + 1e-5f);

    #pragma unroll
    for (int j = 0; j < 4; ++j) {
        int k = tid + 256 * j;
        g_lnT[k * 16 + b] = (a[j] - mu) * rs * lg[k] + lb[k];
    }
}

// ============================================================================
// Kernel 1: h = gelu(LN @ W1 + b1) -> g_hT[k][b]
// 64 CTAs x 512 thr; CTA = 16 cols, 32-way k-split.
// smem: 16384 floats (full lnT), reduction region (8704 floats) overlaps after sync.
// ============================================================================
__global__ __launch_bounds__(512)
void h_kernel(const float* __restrict__ W1, const float* __restrict__ b1) {
    extern __shared__ float s[];
    const int tid = threadIdx.x;
    for (int i = tid; i < 4096; i += 512)          // FIX: full 16384 floats
        ((float4*)s)[i] = ((const float4*)g_lnT)[i];
    __syncthreads();

    const int kg = tid >> 4, cl = tid & 15;   // kg 0..31
    const int col = (blockIdx.x << 4) + cl;

    u64 acc[8];
    #pragma unroll
    for (int j = 0; j < 8; ++j) acc[j] = 0ULL;

    const int k0 = kg * 32;
    #pragma unroll 4
    for (int k = k0; k < k0 + 32; ++k) {
        float w = __ldg(W1 + k * 1024 + col);
        u64 wd = dup2(w);
        const u64* hp = (const u64*)(s + k * 16);
        #pragma unroll
        for (int j = 0; j < 8; ++j) acc[j] = fma2(hp[j], wd, acc[j]);
    }
    __syncthreads();
    #pragma unroll
    for (int j = 0; j < 8; ++j) {
        float f0, f1; upk2(acc[j], f0, f1);
        s[tid * 17 + 2 * j]     = f0;
        s[tid * 17 + 2 * j + 1] = f1;
    }
    __syncthreads();

    if (tid < 256) {
        const int oc = tid & 15, ob = tid >> 4;   // ob = batch 0..15
        const int ocol = (blockIdx.x << 4) + oc;
        float v = b1[ocol];
        #pragma unroll
        for (int g = 0; g < 32; ++g) v += s[(g * 16 + oc) * 17 + ob];
        g_hT[ocol * 16 + ob] = gelu1(v);
    }
}

// ============================================================================
// Kernel 2: w = h @ W2 + b2 -> g_w (transposed [b][f][r][d])
// 256 CTAs x 256 thr; CTA = 128 cols (4/thread via float4), 8-way k-split.
// ============================================================================
#define WPAD 67
__global__ __launch_bounds__(256, 2)
void w_kernel(const float* __restrict__ W2, const float* __restrict__ b2) {
    extern __shared__ float s[];   // 16384 hT floats, then 8*32*67 reduction
    const int tid = threadIdx.x;
    for (int i = tid; i < 4096; i += 256)
        ((float4*)s)[i] = ((const float4*)g_hT)[i];
    __syncthreads();

    const int kg = tid >> 5, cl = tid & 31;
    const int col0 = (blockIdx.x << 7) + cl * 4;

    u64 acc[4][8];
    #pragma unroll
    for (int c = 0; c < 4; ++c)
        #pragma unroll
        for (int j = 0; j < 8; ++j) acc[c][j] = 0ULL;

    const int k0 = kg << 7;
    #pragma unroll 4
    for (int k = k0; k < k0 + 128; ++k) {
        float4 w = __ldg((const float4*)(W2 + (size_t)k * 32768 + col0));
        const u64* hp = (const u64*)(s + k * 16);
        u64 w0 = dup2(w.x), w1 = dup2(w.y), w2 = dup2(w.z), w3 = dup2(w.w);
        #pragma unroll
        for (int j = 0; j < 8; ++j) {
            u64 h2 = hp[j];
            acc[0][j] = fma2(h2, w0, acc[0][j]);
            acc[1][j] = fma2(h2, w1, acc[1][j]);
            acc[2][j] = fma2(h2, w2, acc[2][j]);
            acc[3][j] = fma2(h2, w3, acc[3][j]);
        }
    }
    __syncthreads();   // done reading hT
    #pragma unroll
    for (int c = 0; c < 4; ++c)
        #pragma unroll
        for (int j = 0; j < 8; ++j) {
            float f0, f1; upk2(acc[c][j], f0, f1);
            s[(kg * 32 + cl) * WPAD + c * 16 + 2 * j]     = f0;
            s[(kg * 32 + cl) * WPAD + c * 16 + 2 * j + 1] = f1;
        }
    __syncthreads();

    // 2048 outputs per CTA, 8 per thread; scatter into transposed layout
    const int ocl = tid & 31, og = tid >> 5;
    #pragma unroll
    for (int m = 0; m < 8; ++m) {
        const int f = og * 8 + m;           // f = c*16 + b
        const int c = f >> 4, b = f & 15;
        float v = 0.f;
        #pragma unroll
        for (int g = 0; g < 8; ++g) v += s[(g * 32 + ocl) * WPAD + f];
        const int col = (blockIdx.x << 7) + ocl * 4 + c;
        v += b2[col];
        const int q = col >> 13, idx = col & 8191;
        const int d = idx >> 3, r = idx & 7;
        g_w[b * WSTRIDE + q * 8192 + r * 1024 + d] = v;
    }
}

// ============================================================================
// Kernel 3: fused main path. CTA = 256 thr (8 warps), 4 rows/warp, 32 rows/CTA.
// grid = 512 (16 batches x 32 row-tiles). Factors already [r][d] transposed.
// ============================================================================
__global__ __launch_bounds__(256, 2)
void main_kernel(const float* __restrict__ x, float* __restrict__ out) {
    extern __shared__ float smem[];
    float* sA = smem;            // 8192 floats
    float* sB = smem + 8192;     // 8192 floats

    const int tid  = threadIdx.x;
    const int lane = tid & 31, wrp = tid >> 5;
    const int b    = blockIdx.x >> 5;
    const int row0 = ((blockIdx.x & 31) << 5) + (wrp << 2);
    const float* gw = g_w + b * WSTRIDE;

    // ---- load a1 [r][d] (straight coalesced copy) ----
    for (int i = tid; i < 2048; i += 256)
        ((float4*)sA)[i] = ((const float4*)gw)[i];
    __syncthreads();

    const float* xr = x + (b * 1024 + row0) * 1024;

    // ---- P1: t1[r] per 4 rows (2 packed pairs) ----
    u64 t1[2][8];
    #pragma unroll
    for (int j = 0; j < 2; ++j)
        #pragma unroll
        for (int r = 0; r < 8; ++r) t1[j][r] = 0ULL;

    #pragma unroll 4
    for (int i = 0; i < 32; ++i) {
        const int d = lane + (i << 5);
        float av[8];
        #pragma unroll
        for (int r = 0; r < 8; ++r) av[r] = sA[r * 1024 + d];
        float x0 = __ldg(xr + d);
        float x1 = __ldg(xr + 1024 + d);
        float x2 = __ldg(xr + 2048 + d);
        float x3 = __ldg(xr + 3072 + d);
        u64 xp0 = pk2(x0, x1), xp1 = pk2(x2, x3);
        #pragma unroll
        for (int r = 0; r < 8; ++r) {
            u64 ad = dup2(av[r]);
            t1[0][r] = fma2(xp0, ad, t1[0][r]);
            t1[1][r] = fma2(xp1, ad, t1[1][r]);
        }
    }
    #pragma unroll
    for (int j = 0; j < 2; ++j)
        #pragma unroll
        for (int r = 0; r < 8; ++r) allred2(t1[j][r]);

    // ---- load bb1 -> sA, a2 -> sB ----
    __syncthreads();
    for (int i = tid; i < 2048; i += 256) {
        ((float4*)sA)[i] = ((const float4*)(gw + 8192))[i];
        ((float4*)sB)[i] = ((const float4*)(gw + 16384))[i];
    }
    __syncthreads();

    // ---- P2: t2 ----
    u64 t2[2][8];
    #pragma unroll
    for (int j = 0; j < 2; ++j)
        #pragma unroll
        for (int r = 0; r < 8; ++r) t2[j][r] = 0ULL;

    #pragma unroll 2
    for (int i = 0; i < 32; ++i) {
        const int d = lane + (i << 5);
        float bv[8], av[8];
        #pragma unroll
        for (int r = 0; r < 8; ++r) { bv[r] = sA[r * 1024 + d]; av[r] = sB[r * 1024 + d]; }
        u64 z0 = 0ULL, z1 = 0ULL;
        #pragma unroll
        for (int r = 0; r < 8; ++r) {
            u64 bd = dup2(bv[r]);
            z0 = fma2(t1[0][r], bd, z0);
            z1 = fma2(t1[1][r], bd, z1);
        }
        z0 = gelu2(z0);
        z1 = gelu2(z1);
        #pragma unroll
        for (int r = 0; r < 8; ++r) {
            u64 ad = dup2(av[r]);
            t2[0][r] = fma2(z0, ad, t2[0][r]);
            t2[1][r] = fma2(z1, ad, t2[1][r]);
        }
    }
    #pragma unroll
    for (int j = 0; j < 2; ++j)
        #pragma unroll
        for (int r = 0; r < 8; ++r) allred2(t2[j][r]);

    // ---- load bb2 -> sA ----
    __syncthreads();
    for (int i = tid; i < 2048; i += 256)
        ((float4*)sA)[i] = ((const float4*)(gw + 24576))[i];
    __syncthreads();

    // ---- P3: out = t2 . bb2 + x ----
    float* orow = out + (b * 1024 + row0) * 1024;
    #pragma unroll 4
    for (int i = 0; i < 32; ++i) {
        const int d = lane + (i << 5);
        float bv[8];
        #pragma unroll
        for (int r = 0; r < 8; ++r) bv[r] = sA[r * 1024 + d];
        float x0 = __ldg(xr + d);
        float x1 = __ldg(xr + 1024 + d);
        float x2 = __ldg(xr + 2048 + d);
        float x3 = __ldg(xr + 3072 + d);
        u64 o0 = pk2(x0, x1), o1 = pk2(x2, x3);
        #pragma unroll
        for (int r = 0; r < 8; ++r) {
            u64 bd = dup2(bv[r]);
            o0 = fma2(t2[0][r], bd, o0);
            o1 = fma2(t2[1][r], bd, o1);
        }
        float f0, f1, f2, f3;
        upk2(o0, f0, f1);
        upk2(o1, f2, f3);
        orow[d]        = f0;
        orow[1024 + d] = f1;
        orow[2048 + d] = f2;
        orow[3072 + d] = f3;
    }
}

// ============================================================================
// launch
// ============================================================================
extern "C" void kernel_launch(void* const* d_in, const int* in_sizes, int n_in,
                              void* d_out, int out_size) {
    const float* x    = (const float*)d_in[0];
    const float* ada  = (const float*)d_in[1];
    const float* ln_g = (const float*)d_in[2];
    const float* ln_b = (const float*)d_in[3];
    const float* W1   = (const float*)d_in[4];
    const float* b1   = (const float*)d_in[5];
    const float* W2   = (const float*)d_in[6];
    const float* b2   = (const float*)d_in[7];
    float* out = (float*)d_out;

    const int h_smem = 65536;                   // FIX: full lnT (16384 floats)
    const int w_smem = 8 * 32 * WPAD * 4;       // 68608
    const int m_smem = 16384 * 4;               // 65536

    cudaFuncSetAttribute(h_kernel,    cudaFuncAttributeMaxDynamicSharedMemorySize, h_smem);
    cudaFuncSetAttribute(w_kernel,    cudaFuncAttributeMaxDynamicSharedMemorySize, w_smem);
    cudaFuncSetAttribute(main_kernel, cudaFuncAttributeMaxDynamicSharedMemorySize, m_smem);

    ln_kernel<<<16, 256>>>(ada, ln_g, ln_b);
    h_kernel<<<64, 512, h_smem>>>(W1, b1);
    w_kernel<<<256, 256, w_smem>>>(W2, b2);
    main_kernel<<<512, 256, m_smem>>>(x, out);
}

// round 5
// speedup vs baseline: 2.1328x; 1.6243x over previous
#include <cuda_runtime.h>
#include <cstdint>

typedef unsigned long long u64;

// ---------------- problem constants ----------------
#define BATCH 16
#define WSTRIDE 32768   // per-batch factor block: 4 * 1024 * 8

// ---------------- device scratch ----------------
__device__ float g_lnT[1024 * 16];   // LN(ada) transposed: [k][b]
__device__ float g_hT [1024 * 16];   // h transposed: [k][b]
// factors, PRE-TRANSPOSED: [b][f][r][d], f: 0=a1, 1=bb1, 2=a2, 3=bb2
__device__ float g_w  [16 * 32768];

// ---------------- f32x2 helpers ----------------
__device__ __forceinline__ u64 pk2(float lo, float hi) {
    u64 r; asm("mov.b64 %0, {%1,%2};" : "=l"(r) : "f"(lo), "f"(hi)); return r;
}
__device__ __forceinline__ void upk2(u64 v, float& lo, float& hi) {
    asm("mov.b64 {%0,%1}, %2;" : "=f"(lo), "=f"(hi) : "l"(v));
}
__device__ __forceinline__ u64 dup2(float x) { return pk2(x, x); }
__device__ __forceinline__ u64 fma2(u64 a, u64 b, u64 c) {
    u64 d; asm("fma.rn.f32x2 %0, %1, %2, %3;" : "=l"(d) : "l"(a), "l"(b), "l"(c)); return d;
}
__device__ __forceinline__ u64 mul2(u64 a, u64 b) {
    u64 d; asm("mul.rn.f32x2 %0, %1, %2;" : "=l"(d) : "l"(a), "l"(b)); return d;
}
__device__ __forceinline__ u64 add2(u64 a, u64 b) {
    u64 d; asm("add.rn.f32x2 %0, %1, %2;" : "=l"(d) : "l"(a), "l"(b)); return d;
}
__device__ __forceinline__ float rcpa(float x) {
    float r; asm("rcp.approx.f32 %0, %1;" : "=f"(r) : "f"(x)); return r;
}
__device__ __forceinline__ float ex2a(float x) {
    float r; asm("ex2.approx.f32 %0, %1;" : "=f"(r) : "f"(x)); return r;
}

__device__ __forceinline__ void cp16(unsigned saddr, const float* g) {
    asm volatile("cp.async.cg.shared.global [%0], [%1], 16;" :: "r"(saddr), "l"(g));
}

__device__ __forceinline__ float gelu1(float v) {
    return 0.5f * v * (1.0f + erff(v * 0.7071067811865476f));
}

// exact gelu on packed f32x2 via A&S 7.1.26 erf (abs err 1.5e-7)
__device__ __forceinline__ u64 gelu2(u64 v) {
    u64 s  = mul2(v, dup2(0.7071067811865476f));
    u64 x  = s & 0x7FFFFFFF7FFFFFFFULL;
    u64 dn = fma2(x, dup2(0.3275911f), dup2(1.0f));
    float d0, d1; upk2(dn, d0, d1);
    u64 t  = pk2(rcpa(d0), rcpa(d1));
    u64 p  = fma2(t, dup2(-1.061405429f), dup2(1.453152027f));
    p = fma2(p, t, dup2(-1.421413741f));
    p = fma2(p, t, dup2( 0.284496736f));
    p = fma2(p, t, dup2(-0.254829592f));
    p = mul2(p, t);
    u64 xx = mul2(x, x);
    u64 ea = mul2(xx, dup2(-1.4426950408889634f));
    float e0, e1; upk2(ea, e0, e1);
    u64 e  = pk2(ex2a(e0), ex2a(e1));
    u64 erfa = fma2(p, e, dup2(1.0f));
    u64 sgn  = s & 0x8000000080000000ULL;
    u64 erf  = erfa | sgn;
    u64 h    = fma2(erf, dup2(0.5f), dup2(0.5f));
    return mul2(v, h);
}

__device__ __forceinline__ void allred2(u64& v) {
    #pragma unroll
    for (int off = 16; off > 0; off >>= 1) {
        u64 o = __shfl_xor_sync(0xFFFFFFFFu, v, off);
        v = add2(v, o);
    }
}

// ============================================================================
// Kernel 0: LayerNorm -> g_lnT[k][b]
// ============================================================================
__global__ __launch_bounds__(256)
void ln_kernel(const float* __restrict__ ada, const float* __restrict__ lg,
               const float* __restrict__ lb) {
    __shared__ float red[8];
    const int b = blockIdx.x, tid = threadIdx.x;
    const int lane = tid & 31, wrp = tid >> 5;

    float a[4];
    #pragma unroll
    for (int j = 0; j < 4; ++j) a[j] = ada[b * 1024 + tid + 256 * j];

    float s = a[0] + a[1] + a[2] + a[3];
    #pragma unroll
    for (int off = 16; off > 0; off >>= 1) s += __shfl_xor_sync(~0u, s, off);
    if (lane == 0) red[wrp] = s;
    __syncthreads();
    float mu = 0.f;
    #pragma unroll
    for (int w = 0; w < 8; ++w) mu += red[w];
    mu *= (1.0f / 1024.0f);
    __syncthreads();

    float ss = 0.f;
    #pragma unroll
    for (int j = 0; j < 4; ++j) { float d = a[j] - mu; ss += d * d; }
    #pragma unroll
    for (int off = 16; off > 0; off >>= 1) ss += __shfl_xor_sync(~0u, ss, off);
    if (lane == 0) red[wrp] = ss;
    __syncthreads();
    float var = 0.f;
    #pragma unroll
    for (int w = 0; w < 8; ++w) var += red[w];
    var *= (1.0f / 1024.0f);
    const float rs = rsqrtf(var + 1e-5f);

    #pragma unroll
    for (int j = 0; j < 4; ++j) {
        int k = tid + 256 * j;
        g_lnT[k * 16 + b] = (a[j] - mu) * rs * lg[k] + lb[k];
    }
}

// ============================================================================
// Kernel 1: h = gelu(LN @ W1 + b1) -> g_hT[k][b]
// 64 CTAs x 512 thr; CTA = 16 cols, 32-way k-split.
// ============================================================================
__global__ __launch_bounds__(512)
void h_kernel(const float* __restrict__ W1, const float* __restrict__ b1) {
    extern __shared__ float s[];
    const int tid = threadIdx.x;
    for (int i = tid; i < 4096; i += 512)
        ((float4*)s)[i] = ((const float4*)g_lnT)[i];
    __syncthreads();

    const int kg = tid >> 4, cl = tid & 15;   // kg 0..31
    const int col = (blockIdx.x << 4) + cl;

    u64 acc[8];
    #pragma unroll
    for (int j = 0; j < 8; ++j) acc[j] = 0ULL;

    const int k0 = kg * 32;
    #pragma unroll 4
    for (int k = k0; k < k0 + 32; ++k) {
        float w = __ldg(W1 + k * 1024 + col);
        u64 wd = dup2(w);
        const u64* hp = (const u64*)(s + k * 16);
        #pragma unroll
        for (int j = 0; j < 8; ++j) acc[j] = fma2(hp[j], wd, acc[j]);
    }
    __syncthreads();
    #pragma unroll
    for (int j = 0; j < 8; ++j) {
        float f0, f1; upk2(acc[j], f0, f1);
        s[tid * 17 + 2 * j]     = f0;
        s[tid * 17 + 2 * j + 1] = f1;
    }
    __syncthreads();

    if (tid < 256) {
        const int oc = tid & 15, ob = tid >> 4;   // ob = batch 0..15
        const int ocol = (blockIdx.x << 4) + oc;
        float v = b1[ocol];
        #pragma unroll
        for (int g = 0; g < 32; ++g) v += s[(g * 16 + oc) * 17 + ob];
        g_hT[ocol * 16 + ob] = gelu1(v);
    }
}

// ============================================================================
// Kernel 2: w = h @ W2 + b2 -> g_w (transposed [b][f][r][d])
// 256 CTAs x 256 thr; CTA = 128 cols (4/thread via float4), 8-way k-split.
// ============================================================================
#define WPAD 67
__global__ __launch_bounds__(256, 2)
void w_kernel(const float* __restrict__ W2, const float* __restrict__ b2) {
    extern __shared__ float s[];   // 16384 hT floats, then 8*32*67 reduction
    const int tid = threadIdx.x;
    for (int i = tid; i < 4096; i += 256)
        ((float4*)s)[i] = ((const float4*)g_hT)[i];
    __syncthreads();

    const int kg = tid >> 5, cl = tid & 31;
    const int col0 = (blockIdx.x << 7) + cl * 4;

    u64 acc[4][8];
    #pragma unroll
    for (int c = 0; c < 4; ++c)
        #pragma unroll
        for (int j = 0; j < 8; ++j) acc[c][j] = 0ULL;

    const int k0 = kg << 7;
    #pragma unroll 8
    for (int k = k0; k < k0 + 128; ++k) {
        float4 w = __ldg((const float4*)(W2 + (size_t)k * 32768 + col0));
        const u64* hp = (const u64*)(s + k * 16);
        u64 w0 = dup2(w.x), w1 = dup2(w.y), w2 = dup2(w.z), w3 = dup2(w.w);
        #pragma unroll
        for (int j = 0; j < 8; ++j) {
            u64 h2 = hp[j];
            acc[0][j] = fma2(h2, w0, acc[0][j]);
            acc[1][j] = fma2(h2, w1, acc[1][j]);
            acc[2][j] = fma2(h2, w2, acc[2][j]);
            acc[3][j] = fma2(h2, w3, acc[3][j]);
        }
    }
    __syncthreads();   // done reading hT
    #pragma unroll
    for (int c = 0; c < 4; ++c)
        #pragma unroll
        for (int j = 0; j < 8; ++j) {
            float f0, f1; upk2(acc[c][j], f0, f1);
            s[(kg * 32 + cl) * WPAD + c * 16 + 2 * j]     = f0;
            s[(kg * 32 + cl) * WPAD + c * 16 + 2 * j + 1] = f1;
        }
    __syncthreads();

    // 2048 outputs per CTA, 8 per thread; scatter into transposed layout
    const int ocl = tid & 31, og = tid >> 5;
    #pragma unroll
    for (int m = 0; m < 8; ++m) {
        const int f = og * 8 + m;           // f = c*16 + b
        const int c = f >> 4, b = f & 15;
        float v = 0.f;
        #pragma unroll
        for (int g = 0; g < 8; ++g) v += s[(g * 32 + ocl) * WPAD + f];
        const int col = (blockIdx.x << 7) + ocl * 4 + c;
        v += b2[col];
        const int q = col >> 13, idx = col & 8191;
        const int d = idx >> 3, r = idx & 7;
        g_w[b * WSTRIDE + q * 8192 + r * 1024 + d] = v;
    }
}

// ============================================================================
// Kernel 3: fused main path, fully vectorized (LDS.128/LDG.128/STG.128) with
// cp.async factor prefetch. CTA = 256 thr (8 warps), 4 rows/warp.
// smem: [a1 | bb1 | a2] = 96KB; bb2 overwrites a1 slot after P1.
// grid = 512 (16 batches x 32 row-tiles).
// ============================================================================
__global__ __launch_bounds__(256, 2)
void main_kernel(const float* __restrict__ x, float* __restrict__ out) {
    extern __shared__ float smem[];
    float* sA1 = smem;            // a1, then bb2
    float* sB1 = smem + 8192;     // bb1
    float* sA2 = smem + 16384;    // a2

    const int tid  = threadIdx.x;
    const int lane = tid & 31, wrp = tid >> 5;
    const int b    = blockIdx.x >> 5;
    const int row0 = ((blockIdx.x & 31) << 5) + (wrp << 2);
    const float* gw = g_w + b * WSTRIDE;

    const unsigned sbase = (unsigned)__cvta_generic_to_shared(smem);

    // G1: a1
    for (int i = tid; i < 2048; i += 256)
        cp16(sbase + i * 16, gw + i * 4);
    asm volatile("cp.async.commit_group;");
    // G2: bb1 + a2 (contiguous in g_w)
    for (int i = tid; i < 4096; i += 256)
        cp16(sbase + 32768 + i * 16, gw + 8192 + i * 4);
    asm volatile("cp.async.commit_group;");

    asm volatile("cp.async.wait_group 1;");   // a1 ready
    __syncthreads();

    const float* xr = x + (b * 1024 + row0) * 1024;

    // ---- P1: t1[r] for 4 rows (2 packed pairs), 4 d-cols per lane per iter ----
    u64 t1[2][8];
    #pragma unroll
    for (int j = 0; j < 2; ++j)
        #pragma unroll
        for (int r = 0; r < 8; ++r) t1[j][r] = 0ULL;

    #pragma unroll 2
    for (int i = 0; i < 8; ++i) {
        const int d0 = (lane << 2) + (i << 7);
        float4 a4[8];
        #pragma unroll
        for (int r = 0; r < 8; ++r) a4[r] = *(const float4*)(sA1 + r * 1024 + d0);
        float4 xv[4];
        #pragma unroll
        for (int rr = 0; rr < 4; ++rr) xv[rr] = __ldg((const float4*)(xr + rr * 1024 + d0));
        #pragma unroll
        for (int c = 0; c < 4; ++c) {
            u64 xp0 = pk2(((const float*)&xv[0])[c], ((const float*)&xv[1])[c]);
            u64 xp1 = pk2(((const float*)&xv[2])[c], ((const float*)&xv[3])[c]);
            #pragma unroll
            for (int r = 0; r < 8; ++r) {
                u64 ad = dup2(((const float*)&a4[r])[c]);
                t1[0][r] = fma2(xp0, ad, t1[0][r]);
                t1[1][r] = fma2(xp1, ad, t1[1][r]);
            }
        }
    }
    #pragma unroll
    for (int j = 0; j < 2; ++j)
        #pragma unroll
        for (int r = 0; r < 8; ++r) allred2(t1[j][r]);

    __syncthreads();   // all warps done reading a1

    // G3: bb2 into a1 slot (overlaps with P2)
    for (int i = tid; i < 2048; i += 256)
        cp16(sbase + i * 16, gw + 24576 + i * 4);
    asm volatile("cp.async.commit_group;");

    asm volatile("cp.async.wait_group 1;");   // bb1 + a2 ready
    __syncthreads();

    // ---- P2: t2, 2 d-cols per lane per iter (LDS.64, caps reg pressure) ----
    u64 t2[2][8];
    #pragma unroll
    for (int j = 0; j < 2; ++j)
        #pragma unroll
        for (int r = 0; r < 8; ++r) t2[j][r] = 0ULL;

    #pragma unroll 2
    for (int i = 0; i < 16; ++i) {
        const int d0 = (lane << 1) + (i << 6);
        float2 bv[8];
        #pragma unroll
        for (int r = 0; r < 8; ++r) bv[r] = *(const float2*)(sB1 + r * 1024 + d0);
        u64 z00 = 0ULL, z10 = 0ULL, z01 = 0ULL, z11 = 0ULL;
        #pragma unroll
        for (int r = 0; r < 8; ++r) {
            u64 b0 = dup2(bv[r].x), b1d = dup2(bv[r].y);
            z00 = fma2(t1[0][r], b0,  z00);
            z10 = fma2(t1[1][r], b0,  z10);
            z01 = fma2(t1[0][r], b1d, z01);
            z11 = fma2(t1[1][r], b1d, z11);
        }
        z00 = gelu2(z00); z10 = gelu2(z10);
        z01 = gelu2(z01); z11 = gelu2(z11);
        float2 av[8];
        #pragma unroll
        for (int r = 0; r < 8; ++r) av[r] = *(const float2*)(sA2 + r * 1024 + d0);
        #pragma unroll
        for (int r = 0; r < 8; ++r) {
            u64 a0 = dup2(av[r].x), a1d = dup2(av[r].y);
            t2[0][r] = fma2(z00, a0,  t2[0][r]);
            t2[1][r] = fma2(z10, a0,  t2[1][r]);
            t2[0][r] = fma2(z01, a1d, t2[0][r]);
            t2[1][r] = fma2(z11, a1d, t2[1][r]);
        }
    }
    #pragma unroll
    for (int j = 0; j < 2; ++j)
        #pragma unroll
        for (int r = 0; r < 8; ++r) allred2(t2[j][r]);

    asm volatile("cp.async.wait_group 0;");   // bb2 ready
    __syncthreads();

    // ---- P3: out = t2 . bb2 + x, vectorized ----
    float* orow = out + (b * 1024 + row0) * 1024;
    #pragma unroll 2
    for (int i = 0; i < 8; ++i) {
        const int d0 = (lane << 2) + (i << 7);
        float4 b4[8];
        #pragma unroll
        for (int r = 0; r < 8; ++r) b4[r] = *(const float4*)(sA1 + r * 1024 + d0);
        float4 xv[4];
        #pragma unroll
        for (int rr = 0; rr < 4; ++rr) xv[rr] = __ldg((const float4*)(xr + rr * 1024 + d0));
        float4 o[4];
        #pragma unroll
        for (int c = 0; c < 4; ++c) {
            u64 o0 = pk2(((const float*)&xv[0])[c], ((const float*)&xv[1])[c]);
            u64 o1 = pk2(((const float*)&xv[2])[c], ((const float*)&xv[3])[c]);
            #pragma unroll
            for (int r = 0; r < 8; ++r) {
                u64 bd = dup2(((const float*)&b4[r])[c]);
                o0 = fma2(t2[0][r], bd, o0);
                o1 = fma2(t2[1][r], bd, o1);
            }
            float f0, f1, f2, f3;
            upk2(o0, f0, f1);
            upk2(o1, f2, f3);
            ((float*)&o[0])[c] = f0;
            ((float*)&o[1])[c] = f1;
            ((float*)&o[2])[c] = f2;
            ((float*)&o[3])[c] = f3;
        }
        #pragma unroll
        for (int rr = 0; rr < 4; ++rr)
            *(float4*)(orow + rr * 1024 + d0) = o[rr];
    }
}

// ============================================================================
// launch
// ============================================================================
extern "C" void kernel_launch(void* const* d_in, const int* in_sizes, int n_in,
                              void* d_out, int out_size) {
    const float* x    = (const float*)d_in[0];
    const float* ada  = (const float*)d_in[1];
    const float* ln_g = (const float*)d_in[2];
    const float* ln_b = (const float*)d_in[3];
    const float* W1   = (const float*)d_in[4];
    const float* b1   = (const float*)d_in[5];
    const float* W2   = (const float*)d_in[6];
    const float* b2   = (const float*)d_in[7];
    float* out = (float*)d_out;

    const int h_smem = 65536;
    const int w_smem = 8 * 32 * WPAD * 4;       // 68608
    const int m_smem = 3 * 8192 * 4;            // 98304 (96KB)

    cudaFuncSetAttribute(h_kernel,    cudaFuncAttributeMaxDynamicSharedMemorySize, h_smem);
    cudaFuncSetAttribute(w_kernel,    cudaFuncAttributeMaxDynamicSharedMemorySize, w_smem);
    cudaFuncSetAttribute(main_kernel, cudaFuncAttributeMaxDynamicSharedMemorySize, m_smem);

    ln_kernel<<<16, 256>>>(ada, ln_g, ln_b);
    h_kernel<<<64, 512, h_smem>>>(W1, b1);
    w_kernel<<<256, 256, w_smem>>>(W2, b2);
    main_kernel<<<512, 256, m_smem>>>(x, out);
}